// round 2
// baseline (speedup 1.0000x reference)
#include <cuda_runtime.h>
#include <cstdint>

#define DI __device__ __forceinline__

// ---------- packed fp32x2 FMA (sm_100+): 2 FMA per instruction ----------
DI unsigned long long fdup(float a){
  unsigned long long r;
  asm("mov.b64 %0, {%1, %1};" : "=l"(r) : "f"(a));
  return r;
}
DI void ffma2(unsigned long long& c, unsigned long long a, unsigned long long b){
  asm("fma.rn.f32x2 %0, %1, %2, %0;" : "+l"(c) : "l"(a), "l"(b));
}
DI float2 funpack(unsigned long long v){
  float2 f;
  asm("mov.b64 {%0, %1}, %2;" : "=f"(f.x), "=f"(f.y) : "l"(v));
  return f;
}

// ---------------- device scratch (no allocation allowed) ----------------
__device__ float g_buf1[67108864];   // conv_in out [8,128,256,256]
__device__ float g_buf2[8388608];    // h1 out      [8,256,64,64]
__device__ float g_buf3[524288];     // h2 out      [8,256,16,16]
__device__ float g_buf4[131072];     // h3 out      [8,256,8,8]
__device__ float g_tres[524288];     // residual mid [8,1024,8,8]
__device__ float g_buf5[131072];     // after res block 0
__device__ float g_buf6[131072];     // final lat (NCHW, post-relu)
__device__ float g_part[4194304];    // split-K partials
__device__ float g_se[512];          // ||emb_k||^2
__device__ int   g_idx[512];
__device__ float g_sqn[512];

// =======================================================================
// Implicit-GEMM conv.  C[m][n] = sum_k W[m][k]*im2col(X)[k][n]
// m=out-channel, n=b*OH*OW+oy*OW+ox, k=(ic,ky,kx).  BM=BN=128, BK=8,
// 256 threads, 8x8 per-thread tile, f32x2 packed accumulation,
// double-buffered smem.  MODE 0: direct write (+bias,+relu).
// MODE 1: write split-K partials to `out` ([split][OC][8*OH*OW]).
// =======================================================================
template<int IC,int IH,int IW,int OC,int OH,int OW,
         int KH,int KW,int SH,int SW,int PH,int PW,
         int NSPLIT,bool RELU_IN,int MODE>
__global__ void __launch_bounds__(256,2)
conv_gemm(const float* __restrict__ W, const float* __restrict__ X,
          const float* __restrict__ bias, float* __restrict__ out)
{
  constexpr int BM=128, BN=128, BK=8;
  constexpr int Ktot = IC*KH*KW;
  constexpr int Ksp  = Ktot / NSPLIT;
  constexpr int NT   = Ksp / BK;
  constexpr int OHW  = OH*OW;
  constexpr int Ntot = 8*OHW;
  static_assert(Ksp % BK == 0, "split");

  __shared__ float As[2][BK][BM];
  __shared__ float Bs[2][BK][BN];

  const int tid = threadIdx.x;
  const int n0  = blockIdx.x * BN;
  const int m0  = blockIdx.y * BM;
  const int kb0 = blockIdx.z * Ksp;

  // A-load mapping: 2 threads per m-row, float4 each (covers BK=8)
  const int am = tid >> 1;
  const int ak = (tid & 1) * 4;
  const float* Aptr = W + (m0+am)*Ktot + kb0 + ak;

  // B-gather mapping: 1 k-row, 4 consecutive n per thread
  const int gk = tid >> 5;
  const int gn = (tid & 31) * 4;
  int nbase[4], iy0[4], ix0[4];
#pragma unroll
  for (int j=0;j<4;j++){
    int n = n0 + gn + j;
    int b = n / OHW; int p = n - b*OHW;
    int oy = p / OW; int ox = p - oy*OW;
    iy0[j] = oy*SH - PH; ix0[j] = ox*SW - PW;
    nbase[j] = b*(IC*IH*IW);
  }

  const int tx = (tid & 15) * 8;
  const int ty = (tid >> 4) * 8;

  unsigned long long acc[8][4];
#pragma unroll
  for(int i=0;i<8;i++){
#pragma unroll
    for(int p=0;p<4;p++) acc[i][p]=0ull;
  }

  // prolog: tile 0
  float4 areg = *(const float4*)(Aptr);
  float br[4];
  {
    int kg = kb0 + gk;
    int ic = kg/(KH*KW); int r = kg - ic*(KH*KW); int ky=r/KW; int kx=r-ky*KW;
#pragma unroll
    for(int j=0;j<4;j++){
      int iy=iy0[j]+ky, ix=ix0[j]+kx;
      float v=0.f;
      if((unsigned)iy<(unsigned)IH && (unsigned)ix<(unsigned)IW)
        v = X[nbase[j] + ic*(IH*IW) + iy*IW + ix];
      if(RELU_IN) v = fmaxf(v,0.f);
      br[j]=v;
    }
  }
  As[0][ak+0][am]=areg.x; As[0][ak+1][am]=areg.y;
  As[0][ak+2][am]=areg.z; As[0][ak+3][am]=areg.w;
  *(float4*)&Bs[0][gk][gn] = make_float4(br[0],br[1],br[2],br[3]);
  __syncthreads();

#pragma unroll 1
  for(int t=0;t<NT;t++){
    const int cur = t&1, nxt = cur^1;
    const bool more = (t+1<NT);
    float4 aN; float bN[4];
    if(more){
      aN = *(const float4*)(Aptr + (t+1)*BK);
      int kg = kb0 + (t+1)*BK + gk;
      int ic = kg/(KH*KW); int r = kg - ic*(KH*KW); int ky=r/KW; int kx=r-ky*KW;
#pragma unroll
      for(int j=0;j<4;j++){
        int iy=iy0[j]+ky, ix=ix0[j]+kx;
        float v=0.f;
        if((unsigned)iy<(unsigned)IH && (unsigned)ix<(unsigned)IW)
          v = X[nbase[j] + ic*(IH*IW) + iy*IW + ix];
        if(RELU_IN) v=fmaxf(v,0.f);
        bN[j]=v;
      }
    }
#pragma unroll
    for(int k=0;k<BK;k++){
      float4 a0 = *(const float4*)&As[cur][k][ty];
      float4 a1 = *(const float4*)&As[cur][k][ty+4];
      ulonglong2 B0 = *(const ulonglong2*)&Bs[cur][k][tx];
      ulonglong2 B1 = *(const ulonglong2*)&Bs[cur][k][tx+4];
      float av[8] = {a0.x,a0.y,a0.z,a0.w,a1.x,a1.y,a1.z,a1.w};
#pragma unroll
      for(int i=0;i<8;i++){
        unsigned long long ad = fdup(av[i]);
        ffma2(acc[i][0],ad,B0.x);
        ffma2(acc[i][1],ad,B0.y);
        ffma2(acc[i][2],ad,B1.x);
        ffma2(acc[i][3],ad,B1.y);
      }
    }
    if(more){
      As[nxt][ak+0][am]=aN.x; As[nxt][ak+1][am]=aN.y;
      As[nxt][ak+2][am]=aN.z; As[nxt][ak+3][am]=aN.w;
      *(float4*)&Bs[nxt][gk][gn] = make_float4(bN[0],bN[1],bN[2],bN[3]);
    }
    __syncthreads();
  }

  if(MODE==0){
    // direct: OHW is a multiple of BN here, so the whole tile is one batch b
    const int b = n0 / OHW;
    const int pbase = n0 - b*OHW + tx;
#pragma unroll
    for(int i=0;i<8;i++){
      int m = m0 + ty + i;
      float bv = bias[m];
      float* op = out + ((long)b*OC + m)*OHW + pbase;
#pragma unroll
      for(int p=0;p<4;p++){
        float2 v = funpack(acc[i][p]);
        v.x = fmaxf(v.x+bv,0.f); v.y = fmaxf(v.y+bv,0.f);
        *(float2*)(op + 2*p) = v;
      }
    }
  } else {
#pragma unroll
    for(int i=0;i<8;i++){
      int m = m0 + ty + i;
      float* pp = out + ((long)blockIdx.z*OC + m)*Ntot + n0 + tx;
#pragma unroll
      for(int p=0;p<4;p++){
        *(float2*)(pp + 2*p) = funpack(acc[i][p]);
      }
    }
  }
}

// ---- split-K reduce + bias + residual-add + relu, NCHW write ----
__global__ void epilogue_k(const float* __restrict__ part, const float* __restrict__ bias,
                           const float* __restrict__ add, float* __restrict__ out,
                           int M, int N, int OHW, int nsplit, int relu)
{
  int gid = blockIdx.x*256 + threadIdx.x;
  if(gid >= M*N) return;
  int m = gid / N, n = gid - m*N;
  float s = 0.f;
  for(int sp=0; sp<nsplit; sp++) s += part[((long)sp*M + m)*N + n];
  if(bias) s += bias[m];
  int b = n / OHW, p = n - b*OHW;
  long oa = ((long)b*M + m)*OHW + p;
  if(add) s += add[oa];
  if(relu) s = fmaxf(s, 0.f);
  out[oa] = s;
}

// ---- VQ ----
__global__ void emb_norms_k(const float* __restrict__ emb, float* __restrict__ se){
  int c = blockIdx.x*256 + threadIdx.x;
  const float* e = emb + c*256;
  float s = 0.f;
  for(int k=0;k<256;k++) s += e[k]*e[k];
  se[c] = s;
}

__global__ void vq_rows_k(const float* __restrict__ lat, const float* __restrict__ emb,
                          const float* __restrict__ se, int* __restrict__ idxo,
                          float* __restrict__ sqo)
{
  __shared__ float sl[256];
  __shared__ float sval[256];
  __shared__ int   sidx[256];
  int r = blockIdx.x, t = threadIdx.x;
  int b = r >> 6, p = r & 63;
  sl[t] = lat[((b<<8) + t)*64 + p];
  __syncthreads();
  float fn = 0.f;
  for(int k=0;k<256;k++) fn += sl[k]*sl[k];
  float best = 3.402823e38f; int bi = 0;
#pragma unroll
  for(int cc=0; cc<2; cc++){
    int c = t + cc*256;
    const float* er = emb + c*256;
    float dot = 0.f;
    for(int k=0;k<256;k++) dot = fmaf(er[k], sl[k], dot);
    float d = fn + se[c] - 2.f*dot;
    if(d < best){ best = d; bi = c; }
  }
  sval[t]=best; sidx[t]=bi;
  __syncthreads();
  for(int s=128;s>0;s>>=1){
    if(t<s){
      float v2=sval[t+s]; int i2=sidx[t+s];
      if(v2<sval[t] || (v2==sval[t] && i2<sidx[t])){ sval[t]=v2; sidx[t]=i2; }
    }
    __syncthreads();
  }
  int w = sidx[0];
  if(t==0) idxo[r]=w;
  __syncthreads();
  float diff = emb[w*256 + t] - sl[t];
  sval[t] = diff*diff;
  __syncthreads();
  for(int s=128;s>0;s>>=1){
    if(t<s) sval[t]+=sval[t+s];
    __syncthreads();
  }
  if(t==0) sqo[r]=sval[0];
}

__global__ void write_quant_k(const int* __restrict__ idx, const float* __restrict__ emb,
                              float* __restrict__ out){
  int gid = blockIdx.x*256 + threadIdx.x;   // 131072 total
  int p = gid & 63;
  int c = (gid >> 6) & 255;
  int b = gid >> 14;
  out[gid] = emb[idx[(b<<6)+p]*256 + c];
}

__global__ void finalize_k(const int* __restrict__ idx, const float* __restrict__ sq,
                           float* __restrict__ out2){
  __shared__ float sh[512];
  __shared__ float ss[512];
  int t = threadIdx.x;   // 512 threads
  int cnt = 0;
  for(int r=0;r<512;r++) cnt += (idx[r]==t) ? 1 : 0;
  float pr = (float)cnt * (1.f/512.f);
  sh[t] = -pr * logf(pr + 1e-10f);
  ss[t] = sq[t];
  __syncthreads();
  for(int s=256;s>0;s>>=1){
    if(t<s){ sh[t]+=sh[t+s]; ss[t]+=ss[t+s]; }
    __syncthreads();
  }
  if(t==0){
    out2[0] = 2.f * ss[0] * (1.f/131072.f);  // q_loss + BETA*e_loss
    out2[1] = expf(sh[0]);
  }
}

// ---------------- host ----------------
template<int IC,int IH,int IW,int OC,int OH,int OW,int KH,int KW,
         int SH,int SW,int PH,int PW,int NSPLIT,bool RIN,int MODE>
static void launch_conv(const float* W, const float* X, const float* bias, float* out){
  dim3 g((8*OH*OW)/128, OC/128, NSPLIT);
  conv_gemm<IC,IH,IW,OC,OH,OW,KH,KW,SH,SW,PH,PW,NSPLIT,RIN,MODE><<<g,256>>>(W,X,bias,out);
}

extern "C" void kernel_launch(void* const* d_in, const int* in_sizes, int n_in,
                              void* d_out, int out_size)
{
  const float* x     = (const float*)d_in[0];
  const float* w_in  = (const float*)d_in[1];
  const float* b_in  = (const float*)d_in[2];
  const float* w_h1  = (const float*)d_in[3];
  const float* b_h1  = (const float*)d_in[4];
  const float* w_h2  = (const float*)d_in[5];
  const float* b_h2  = (const float*)d_in[6];
  const float* w_h3  = (const float*)d_in[7];
  const float* b_h3  = (const float*)d_in[8];
  const float* r0_w1 = (const float*)d_in[9];
  const float* r0_w2 = (const float*)d_in[10];
  const float* r1_w1 = (const float*)d_in[11];
  const float* r1_w2 = (const float*)d_in[12];
  const float* emb   = (const float*)d_in[13];
  float* out = (float*)d_out;

  float *b1,*b2,*b3,*b4,*b5,*b6,*tr,*pp,*se,*sq; int* gi;
  cudaGetSymbolAddress((void**)&b1, g_buf1);
  cudaGetSymbolAddress((void**)&b2, g_buf2);
  cudaGetSymbolAddress((void**)&b3, g_buf3);
  cudaGetSymbolAddress((void**)&b4, g_buf4);
  cudaGetSymbolAddress((void**)&b5, g_buf5);
  cudaGetSymbolAddress((void**)&b6, g_buf6);
  cudaGetSymbolAddress((void**)&tr, g_tres);
  cudaGetSymbolAddress((void**)&pp, g_part);
  cudaGetSymbolAddress((void**)&se, g_se);
  cudaGetSymbolAddress((void**)&sq, g_sqn);
  cudaGetSymbolAddress((void**)&gi, g_idx);

  // conv_in: [8,3,512,512] -> [8,128,256,256], 4x4 s2 p1, bias+relu, direct
  launch_conv<3,512,512, 128,256,256, 4,4, 2,2, 1,1, 1,false,0>(w_in, x, b_in, b1);
  // h1: -> [8,256,64,64], 7x7 s4 p2, bias+relu, direct
  launch_conv<128,256,256, 256,64,64, 7,7, 4,4, 2,2, 1,false,0>(w_h1, b1, b_h1, b2);
  // h2: -> [8,256,16,16], 7x7 s4 p2, split-K 4
  launch_conv<256,64,64, 256,16,16, 7,7, 4,4, 2,2, 4,false,1>(w_h2, b2, nullptr, pp);
  epilogue_k<<<(256*2048+255)/256,256>>>(pp, b_h2, nullptr, b3, 256, 2048, 256, 4, 1);
  // h3: -> [8,256,8,8], 3x3 s2 p1, split-K 16
  launch_conv<256,16,16, 256,8,8, 3,3, 2,2, 1,1, 16,false,1>(w_h3, b3, nullptr, pp);
  epilogue_k<<<(256*512+255)/256,256>>>(pp, b_h3, nullptr, b4, 256, 512, 64, 16, 1);

  // residual block 0 (input b4 >= 0, relu(h)==h)
  launch_conv<256,8,8, 1024,8,8, 1,3, 1,1, 0,1, 8,false,1>(r0_w1, b4, nullptr, pp);
  epilogue_k<<<(1024*512+255)/256,256>>>(pp, nullptr, nullptr, tr, 1024, 512, 64, 8, 1);
  launch_conv<1024,8,8, 256,8,8, 1,1, 1,1, 0,0, 8,false,1>(r0_w2, tr, nullptr, pp);
  epilogue_k<<<(256*512+255)/256,256>>>(pp, nullptr, b4, b5, 256, 512, 64, 8, 0);

  // residual block 1 (b5 may be negative -> relu on gather)
  launch_conv<256,8,8, 1024,8,8, 1,3, 1,1, 0,1, 8,true,1>(r1_w1, b5, nullptr, pp);
  epilogue_k<<<(1024*512+255)/256,256>>>(pp, nullptr, nullptr, tr, 1024, 512, 64, 8, 1);
  launch_conv<1024,8,8, 256,8,8, 1,1, 1,1, 0,0, 8,false,1>(r1_w2, tr, nullptr, pp);
  // h = relu(b5 + t)  (final relu before VQ folded here)
  epilogue_k<<<(256*512+255)/256,256>>>(pp, nullptr, b5, b6, 256, 512, 64, 8, 1);

  // VQ
  emb_norms_k<<<2,256>>>(emb, se);
  vq_rows_k<<<512,256>>>(b6, emb, se, gi, sq);
  write_quant_k<<<512,256>>>(gi, emb, out);
  finalize_k<<<1,512>>>(gi, sq, out + 131072);
}

// round 3
// speedup vs baseline: 1.1409x; 1.1409x over previous
#include <cuda_runtime.h>
#include <cstdint>

#define DI __device__ __forceinline__

// ---------- packed fp32x2 FMA (sm_100+): 2 FMA per instruction ----------
DI unsigned long long fdup(float a){
  unsigned long long r;
  asm("mov.b64 %0, {%1, %1};" : "=l"(r) : "f"(a));
  return r;
}
DI void ffma2(unsigned long long& c, unsigned long long a, unsigned long long b){
  asm("fma.rn.f32x2 %0, %1, %2, %0;" : "+l"(c) : "l"(a), "l"(b));
}
DI float2 funpack(unsigned long long v){
  float2 f;
  asm("mov.b64 {%0, %1}, %2;" : "=f"(f.x), "=f"(f.y) : "l"(v));
  return f;
}

// ---------------- device scratch (no allocation allowed) ----------------
__device__ float g_buf1[67108864];   // conv_in out [8,128,256,256]
__device__ float g_buf2[8388608];    // h1 out      [8,256,64,64]
__device__ float g_buf3[524288];     // h2 out      [8,256,16,16]
__device__ float g_buf4[131072];     // h3 out      [8,256,8,8]
__device__ float g_tres[524288];     // residual mid [8,1024,8,8]
__device__ float g_buf5[131072];     // after res block 0
__device__ float g_buf6[131072];     // final lat (NCHW, post-relu)
__device__ float g_part[4194304];    // split-K partials
__device__ float g_se[512];          // ||emb_k||^2
__device__ int   g_idx[512];
__device__ float g_sqn[512];

__global__ void noop_k(){}

// =======================================================================
// Implicit-GEMM conv.  C[m][n] = sum_k W[m][k]*im2col(X)[k][n]
// BM=BN=128, BK=8, 256 threads.  Per-thread tile = rows {ty4+0..3, ty4+64..67}
// x cols {tx4+0..3, tx4+64..67}  (split tiling -> conflict-free LDS.128).
// f32x2 packed accumulation, double-buffered smem.
// MODE 0: direct write (+bias,+relu).  MODE 1: split-K partials.
// =======================================================================
template<int IC,int IH,int IW,int OC,int OH,int OW,
         int KH,int KW,int SH,int SW,int PH,int PW,
         int NSPLIT,bool RELU_IN,int MODE>
__global__ void __launch_bounds__(256,2)
conv_gemm(const float* __restrict__ W, const float* __restrict__ X,
          const float* __restrict__ bias, float* __restrict__ out)
{
  constexpr int BM=128, BN=128, BK=8;
  constexpr int Ktot = IC*KH*KW;
  constexpr int Ksp  = Ktot / NSPLIT;
  constexpr int NT   = Ksp / BK;
  constexpr int OHW  = OH*OW;
  constexpr int Ntot = 8*OHW;
  static_assert(Ksp % BK == 0, "split");

  __shared__ float As[2][BK][BM];
  __shared__ float Bs[2][BK][BN];

  const int tid = threadIdx.x;
  const int n0  = blockIdx.x * BN;
  const int m0  = blockIdx.y * BM;
  const int kb0 = blockIdx.z * Ksp;

  // A-load mapping: 2 threads per m-row, float4 each (covers BK=8)
  const int am = tid >> 1;
  const int ak = (tid & 1) * 4;
  const float* Aptr = W + (m0+am)*Ktot + kb0 + ak;

  // B-gather mapping: 1 k-row, 4 consecutive n per thread
  const int gk = tid >> 5;
  const int gn = (tid & 31) * 4;
  int nbase[4], iy0[4], ix0[4];
#pragma unroll
  for (int j=0;j<4;j++){
    int n = n0 + gn + j;
    int b = n / OHW; int p = n - b*OHW;
    int oy = p / OW; int ox = p - oy*OW;
    iy0[j] = oy*SH - PH; ix0[j] = ox*SW - PW;
    nbase[j] = b*(IC*IH*IW);
  }

  const int tx4 = (tid & 15) * 4;   // cols tx4..tx4+3 and +64
  const int ty4 = (tid >> 4) * 4;   // rows ty4..ty4+3 and +64

  unsigned long long acc[8][4];
#pragma unroll
  for(int i=0;i<8;i++){
#pragma unroll
    for(int p=0;p<4;p++) acc[i][p]=0ull;
  }

  // prolog: tile 0
  float4 areg = *(const float4*)(Aptr);
  float br[4];
  {
    int kg = kb0 + gk;
    int ic = kg/(KH*KW); int r = kg - ic*(KH*KW); int ky=r/KW; int kx=r-ky*KW;
#pragma unroll
    for(int j=0;j<4;j++){
      int iy=iy0[j]+ky, ix=ix0[j]+kx;
      float v=0.f;
      if((unsigned)iy<(unsigned)IH && (unsigned)ix<(unsigned)IW)
        v = X[nbase[j] + ic*(IH*IW) + iy*IW + ix];
      if(RELU_IN) v = fmaxf(v,0.f);
      br[j]=v;
    }
  }
  As[0][ak+0][am]=areg.x; As[0][ak+1][am]=areg.y;
  As[0][ak+2][am]=areg.z; As[0][ak+3][am]=areg.w;
  *(float4*)&Bs[0][gk][gn] = make_float4(br[0],br[1],br[2],br[3]);
  __syncthreads();

#pragma unroll 1
  for(int t=0;t<NT;t++){
    const int cur = t&1, nxt = cur^1;
    const bool more = (t+1<NT);
    float4 aN; float bN[4];
    if(more){
      aN = *(const float4*)(Aptr + (t+1)*BK);
      int kg = kb0 + (t+1)*BK + gk;
      int ic = kg/(KH*KW); int r = kg - ic*(KH*KW); int ky=r/KW; int kx=r-ky*KW;
#pragma unroll
      for(int j=0;j<4;j++){
        int iy=iy0[j]+ky, ix=ix0[j]+kx;
        float v=0.f;
        if((unsigned)iy<(unsigned)IH && (unsigned)ix<(unsigned)IW)
          v = X[nbase[j] + ic*(IH*IW) + iy*IW + ix];
        if(RELU_IN) v=fmaxf(v,0.f);
        bN[j]=v;
      }
    }
#pragma unroll
    for(int k=0;k<BK;k++){
      float4 a0 = *(const float4*)&As[cur][k][ty4];
      float4 a1 = *(const float4*)&As[cur][k][ty4+64];
      ulonglong2 B0 = *(const ulonglong2*)&Bs[cur][k][tx4];
      ulonglong2 B1 = *(const ulonglong2*)&Bs[cur][k][tx4+64];
      float av[8] = {a0.x,a0.y,a0.z,a0.w,a1.x,a1.y,a1.z,a1.w};
#pragma unroll
      for(int i=0;i<8;i++){
        unsigned long long ad = fdup(av[i]);
        ffma2(acc[i][0],ad,B0.x);
        ffma2(acc[i][1],ad,B0.y);
        ffma2(acc[i][2],ad,B1.x);
        ffma2(acc[i][3],ad,B1.y);
      }
    }
    if(more){
      As[nxt][ak+0][am]=aN.x; As[nxt][ak+1][am]=aN.y;
      As[nxt][ak+2][am]=aN.z; As[nxt][ak+3][am]=aN.w;
      *(float4*)&Bs[nxt][gk][gn] = make_float4(bN[0],bN[1],bN[2],bN[3]);
    }
    __syncthreads();
  }

  if(MODE==0){
    // direct: OHW is a multiple of BN here, so whole tile is one batch b
    const int b = n0 / OHW;
    const int pbase = n0 - b*OHW;
#pragma unroll
    for(int i=0;i<8;i++){
      int m = m0 + ty4 + ((i<4) ? i : (60 + i));
      float bv = bias[m];
      float* op = out + ((long)b*OC + m)*OHW + pbase;
      float2 v0 = funpack(acc[i][0]); float2 v1 = funpack(acc[i][1]);
      float2 v2 = funpack(acc[i][2]); float2 v3 = funpack(acc[i][3]);
      float4 lo = make_float4(fmaxf(v0.x+bv,0.f), fmaxf(v0.y+bv,0.f),
                              fmaxf(v1.x+bv,0.f), fmaxf(v1.y+bv,0.f));
      float4 hi = make_float4(fmaxf(v2.x+bv,0.f), fmaxf(v2.y+bv,0.f),
                              fmaxf(v3.x+bv,0.f), fmaxf(v3.y+bv,0.f));
      *(float4*)(op + tx4)      = lo;
      *(float4*)(op + tx4 + 64) = hi;
    }
  } else {
#pragma unroll
    for(int i=0;i<8;i++){
      int m = m0 + ty4 + ((i<4) ? i : (60 + i));
      float* pp = out + ((long)blockIdx.z*OC + m)*Ntot + n0;
      float2 v0 = funpack(acc[i][0]); float2 v1 = funpack(acc[i][1]);
      float2 v2 = funpack(acc[i][2]); float2 v3 = funpack(acc[i][3]);
      *(float4*)(pp + tx4)      = make_float4(v0.x,v0.y,v1.x,v1.y);
      *(float4*)(pp + tx4 + 64) = make_float4(v2.x,v2.y,v3.x,v3.y);
    }
  }
}

// ---- split-K reduce + bias + residual-add + relu, NCHW write ----
__global__ void epilogue_k(const float* __restrict__ part, const float* __restrict__ bias,
                           const float* __restrict__ add, float* __restrict__ out,
                           int M, int N, int OHW, int nsplit, int relu)
{
  int gid = blockIdx.x*256 + threadIdx.x;
  if(gid >= M*N) return;
  int m = gid / N, n = gid - m*N;
  float s = 0.f;
  for(int sp=0; sp<nsplit; sp++) s += part[((long)sp*M + m)*N + n];
  if(bias) s += bias[m];
  int b = n / OHW, p = n - b*OHW;
  long oa = ((long)b*M + m)*OHW + p;
  if(add) s += add[oa];
  if(relu) s = fmaxf(s, 0.f);
  out[oa] = s;
}

// ---- VQ ----
__global__ void emb_norms_k(const float* __restrict__ emb, float* __restrict__ se){
  int c = blockIdx.x*256 + threadIdx.x;
  const float* e = emb + c*256;
  float s = 0.f;
  for(int k=0;k<256;k++) s += e[k]*e[k];
  se[c] = s;
}

__global__ void vq_rows_k(const float* __restrict__ lat, const float* __restrict__ emb,
                          const float* __restrict__ se, int* __restrict__ idxo,
                          float* __restrict__ sqo)
{
  __shared__ float sl[256];
  __shared__ float sval[256];
  __shared__ int   sidx[256];
  int r = blockIdx.x, t = threadIdx.x;
  int b = r >> 6, p = r & 63;
  sl[t] = lat[((b<<8) + t)*64 + p];
  __syncthreads();
  float fn = 0.f;
  for(int k=0;k<256;k++) fn += sl[k]*sl[k];
  float best = 3.402823e38f; int bi = 0;
#pragma unroll
  for(int cc=0; cc<2; cc++){
    int c = t + cc*256;
    const float* er = emb + c*256;
    float dot = 0.f;
    for(int k=0;k<256;k++) dot = fmaf(er[k], sl[k], dot);
    float d = fn + se[c] - 2.f*dot;
    if(d < best){ best = d; bi = c; }
  }
  sval[t]=best; sidx[t]=bi;
  __syncthreads();
  for(int s=128;s>0;s>>=1){
    if(t<s){
      float v2=sval[t+s]; int i2=sidx[t+s];
      if(v2<sval[t] || (v2==sval[t] && i2<sidx[t])){ sval[t]=v2; sidx[t]=i2; }
    }
    __syncthreads();
  }
  int w = sidx[0];
  if(t==0) idxo[r]=w;
  __syncthreads();
  float diff = emb[w*256 + t] - sl[t];
  sval[t] = diff*diff;
  __syncthreads();
  for(int s=128;s>0;s>>=1){
    if(t<s) sval[t]+=sval[t+s];
    __syncthreads();
  }
  if(t==0) sqo[r]=sval[0];
}

__global__ void write_quant_k(const int* __restrict__ idx, const float* __restrict__ emb,
                              float* __restrict__ out){
  int gid = blockIdx.x*256 + threadIdx.x;   // 131072 total
  int p = gid & 63;
  int c = (gid >> 6) & 255;
  int b = gid >> 14;
  out[gid] = emb[idx[(b<<6)+p]*256 + c];
}

__global__ void finalize_k(const int* __restrict__ idx, const float* __restrict__ sq,
                           float* __restrict__ out2){
  __shared__ float sh[512];
  __shared__ float ss[512];
  int t = threadIdx.x;   // 512 threads
  int cnt = 0;
  for(int r=0;r<512;r++) cnt += (idx[r]==t) ? 1 : 0;
  float pr = (float)cnt * (1.f/512.f);
  sh[t] = -pr * logf(pr + 1e-10f);
  ss[t] = sq[t];
  __syncthreads();
  for(int s=256;s>0;s>>=1){
    if(t<s){ sh[t]+=sh[t+s]; ss[t]+=ss[t+s]; }
    __syncthreads();
  }
  if(t==0){
    out2[0] = 2.f * ss[0] * (1.f/131072.f);  // q_loss + BETA*e_loss
    out2[1] = expf(sh[0]);
  }
}

// ---------------- host ----------------
template<int IC,int IH,int IW,int OC,int OH,int OW,int KH,int KW,
         int SH,int SW,int PH,int PW,int NSPLIT,bool RIN,int MODE>
static void launch_conv(const float* W, const float* X, const float* bias, float* out){
  dim3 g((8*OH*OW)/128, OC/128, NSPLIT);
  conv_gemm<IC,IH,IW,OC,OH,OW,KH,KW,SH,SW,PH,PW,NSPLIT,RIN,MODE><<<g,256>>>(W,X,bias,out);
}

extern "C" void kernel_launch(void* const* d_in, const int* in_sizes, int n_in,
                              void* d_out, int out_size)
{
  const float* x     = (const float*)d_in[0];
  const float* w_in  = (const float*)d_in[1];
  const float* b_in  = (const float*)d_in[2];
  const float* w_h1  = (const float*)d_in[3];
  const float* b_h1  = (const float*)d_in[4];
  const float* w_h2  = (const float*)d_in[5];
  const float* b_h2  = (const float*)d_in[6];
  const float* w_h3  = (const float*)d_in[7];
  const float* b_h3  = (const float*)d_in[8];
  const float* r0_w1 = (const float*)d_in[9];
  const float* r0_w2 = (const float*)d_in[10];
  const float* r1_w1 = (const float*)d_in[11];
  const float* r1_w2 = (const float*)d_in[12];
  const float* emb   = (const float*)d_in[13];
  float* out = (float*)d_out;

  float *b1,*b2,*b3,*b4,*b5,*b6,*tr,*pp,*se,*sq; int* gi;
  cudaGetSymbolAddress((void**)&b1, g_buf1);
  cudaGetSymbolAddress((void**)&b2, g_buf2);
  cudaGetSymbolAddress((void**)&b3, g_buf3);
  cudaGetSymbolAddress((void**)&b4, g_buf4);
  cudaGetSymbolAddress((void**)&b5, g_buf5);
  cudaGetSymbolAddress((void**)&b6, g_buf6);
  cudaGetSymbolAddress((void**)&tr, g_tres);
  cudaGetSymbolAddress((void**)&pp, g_part);
  cudaGetSymbolAddress((void**)&se, g_se);
  cudaGetSymbolAddress((void**)&sq, g_sqn);
  cudaGetSymbolAddress((void**)&gi, g_idx);

  // launches 0-4: padding so h1 is launch index 5 (ncu -s 5 -c 1 profiles h1)
  noop_k<<<1,32>>>();
  noop_k<<<1,32>>>();
  noop_k<<<1,32>>>();
  emb_norms_k<<<2,256>>>(emb, se);
  // conv_in: [8,3,512,512] -> [8,128,256,256], 4x4 s2 p1, bias+relu, direct
  launch_conv<3,512,512, 128,256,256, 4,4, 2,2, 1,1, 1,false,0>(w_in, x, b_in, b1);
  // h1 (launch 5): -> [8,256,64,64], 7x7 s4 p2, bias+relu, direct
  launch_conv<128,256,256, 256,64,64, 7,7, 4,4, 2,2, 1,false,0>(w_h1, b1, b_h1, b2);
  // h2: -> [8,256,16,16], 7x7 s4 p2, split-K 8
  launch_conv<256,64,64, 256,16,16, 7,7, 4,4, 2,2, 8,false,1>(w_h2, b2, nullptr, pp);
  epilogue_k<<<(256*2048+255)/256,256>>>(pp, b_h2, nullptr, b3, 256, 2048, 256, 8, 1);
  // h3: -> [8,256,8,8], 3x3 s2 p1, split-K 16
  launch_conv<256,16,16, 256,8,8, 3,3, 2,2, 1,1, 16,false,1>(w_h3, b3, nullptr, pp);
  epilogue_k<<<(256*512+255)/256,256>>>(pp, b_h3, nullptr, b4, 256, 512, 64, 16, 1);

  // residual block 0 (input b4 >= 0, relu(h)==h)
  launch_conv<256,8,8, 1024,8,8, 1,3, 1,1, 0,1, 8,false,1>(r0_w1, b4, nullptr, pp);
  epilogue_k<<<(1024*512+255)/256,256>>>(pp, nullptr, nullptr, tr, 1024, 512, 64, 8, 1);
  launch_conv<1024,8,8, 256,8,8, 1,1, 1,1, 0,0, 8,false,1>(r0_w2, tr, nullptr, pp);
  epilogue_k<<<(256*512+255)/256,256>>>(pp, nullptr, b4, b5, 256, 512, 64, 8, 0);

  // residual block 1 (b5 may be negative -> relu on gather)
  launch_conv<256,8,8, 1024,8,8, 1,3, 1,1, 0,1, 8,true,1>(r1_w1, b5, nullptr, pp);
  epilogue_k<<<(1024*512+255)/256,256>>>(pp, nullptr, nullptr, tr, 1024, 512, 64, 8, 1);
  launch_conv<1024,8,8, 256,8,8, 1,1, 1,1, 0,0, 8,false,1>(r1_w2, tr, nullptr, pp);
  // h = relu(b5 + t)  (final relu before VQ folded here)
  epilogue_k<<<(256*512+255)/256,256>>>(pp, nullptr, b5, b6, 256, 512, 64, 8, 1);

  // VQ
  vq_rows_k<<<512,256>>>(b6, emb, se, gi, sq);
  write_quant_k<<<512,256>>>(gi, emb, out);
  finalize_k<<<1,512>>>(gi, sq, out + 131072);
}

// round 4
// speedup vs baseline: 1.1810x; 1.0352x over previous
#include <cuda_runtime.h>
#include <cstdint>

#define DI __device__ __forceinline__

// ---------- packed fp32x2 FMA (sm_100+): 2 FMA per instruction ----------
DI unsigned long long fdup(float a){
  unsigned long long r;
  asm("mov.b64 %0, {%1, %1};" : "=l"(r) : "f"(a));
  return r;
}
DI void ffma2(unsigned long long& c, unsigned long long a, unsigned long long b){
  asm("fma.rn.f32x2 %0, %1, %2, %0;" : "+l"(c) : "l"(a), "l"(b));
}
DI float2 funpack(unsigned long long v){
  float2 f;
  asm("mov.b64 {%0, %1}, %2;" : "=f"(f.x), "=f"(f.y) : "l"(v));
  return f;
}

// ---------------- device scratch (zero-initialized; no allocation) ----------------
__device__ float g_buf1[69222400];   // conv_in out PADDED [8,128,260,260] (borders stay 0)
__device__ float g_buf2[8388608];    // h1 out      [8,256,64,64]
__device__ float g_buf3[524288];     // h2 out      [8,256,16,16]
__device__ float g_buf4[131072];     // h3 out      [8,256,8,8]
__device__ float g_tres[524288];     // residual mid [8,1024,8,8]
__device__ float g_buf5[131072];     // after res block 0
__device__ float g_buf6[131072];     // final lat (NCHW, post-relu)
__device__ float g_part[4194304];    // split-K partials
__device__ float g_embT[131072];     // emb transposed [256][512]
__device__ float g_se[512];          // ||emb_k||^2
__device__ int   g_idx[512];
__device__ float g_sqn[512];

// =======================================================================
// Implicit-GEMM conv.  BM=BN=128, BK=8, 256 threads, 8x8 split tile
// (conflict-free LDS.128), f32x2 packed accumulation, double-buffered smem.
// MODE 0: direct NCHW write (+bias,+relu)
// MODE 1: split-K partials
// MODE 2: direct write into PADDED layout [b][OC][OH+4][OW+4] offset +2
// PADIN : X is padded [b][IC][IH+4][IW+4] offset +2 -> no bounds checks
// =======================================================================
template<int IC,int IH,int IW,int OC,int OH,int OW,
         int KH,int KW,int SH,int SW,int PH,int PW,
         int NSPLIT,bool RELU_IN,int MODE,bool PADIN>
__global__ void __launch_bounds__(256,2)
conv_gemm(const float* __restrict__ W, const float* __restrict__ X,
          const float* __restrict__ bias, float* __restrict__ out)
{
  constexpr int BM=128, BN=128, BK=8;
  constexpr int Ktot = IC*KH*KW;
  constexpr int Ksp  = Ktot / NSPLIT;
  constexpr int NT   = Ksp / BK;
  constexpr int OHW  = OH*OW;
  constexpr int Ntot = 8*OHW;
  constexpr int PIH  = IH+4, PIW = IW+4;
  static_assert(Ksp % BK == 0, "split");

  __shared__ float As[2][BK][BM];
  __shared__ float Bs[2][BK][BN];

  const int tid = threadIdx.x;
  const int n0  = blockIdx.x * BN;
  const int m0  = blockIdx.y * BM;
  const int kb0 = blockIdx.z * Ksp;

  // A-load: 2 threads per m-row, float4 each
  const int am = tid >> 1;
  const int ak = (tid & 1) * 4;
  const float* Aptr = W + (m0+am)*Ktot + kb0 + ak;

  // B-gather: 1 k-row, 4 consecutive n per thread
  const int gk = tid >> 5;
  const int gn = (tid & 31) * 4;
  int pbase[4];          // PADIN: fused base; else nbase
  int iy0[4], ix0[4];
#pragma unroll
  for (int j=0;j<4;j++){
    int n = n0 + gn + j;
    int b = n / OHW; int p = n - b*OHW;
    int oy = p / OW; int ox = p - oy*OW;
    int iy = oy*SH - PH, ix = ox*SW - PW;
    if(PADIN){
      pbase[j] = b*(IC*PIH*PIW) + (iy+2)*PIW + (ix+2);
    } else {
      iy0[j] = iy; ix0[j] = ix;
      pbase[j] = b*(IC*IH*IW);
    }
  }

  const int tx4 = (tid & 15) * 4;
  const int ty4 = (tid >> 4) * 4;

  unsigned long long acc[8][4];
#pragma unroll
  for(int i=0;i<8;i++){
#pragma unroll
    for(int p=0;p<4;p++) acc[i][p]=0ull;
  }

  // prolog: tile 0
  float4 areg = *(const float4*)(Aptr);
  float br[4];
  {
    int kg = kb0 + gk;
    int ic = kg/(KH*KW); int r = kg - ic*(KH*KW); int ky=r/KW; int kx=r-ky*KW;
#pragma unroll
    for(int j=0;j<4;j++){
      float v;
      if(PADIN){
        v = X[pbase[j] + ic*(PIH*PIW) + ky*PIW + kx];
      } else {
        int iy=iy0[j]+ky, ix=ix0[j]+kx;
        v = 0.f;
        if((unsigned)iy<(unsigned)IH && (unsigned)ix<(unsigned)IW)
          v = X[pbase[j] + ic*(IH*IW) + iy*IW + ix];
        if(RELU_IN) v = fmaxf(v,0.f);
      }
      br[j]=v;
    }
  }
  As[0][ak+0][am]=areg.x; As[0][ak+1][am]=areg.y;
  As[0][ak+2][am]=areg.z; As[0][ak+3][am]=areg.w;
  *(float4*)&Bs[0][gk][gn] = make_float4(br[0],br[1],br[2],br[3]);
  __syncthreads();

#pragma unroll 1
  for(int t=0;t<NT;t++){
    const int cur = t&1, nxt = cur^1;
    const bool more = (t+1<NT);
    float4 aN; float bN[4];
    if(more){
      aN = *(const float4*)(Aptr + (t+1)*BK);
      int kg = kb0 + (t+1)*BK + gk;
      int ic = kg/(KH*KW); int r = kg - ic*(KH*KW); int ky=r/KW; int kx=r-ky*KW;
#pragma unroll
      for(int j=0;j<4;j++){
        float v;
        if(PADIN){
          v = X[pbase[j] + ic*(PIH*PIW) + ky*PIW + kx];
        } else {
          int iy=iy0[j]+ky, ix=ix0[j]+kx;
          v = 0.f;
          if((unsigned)iy<(unsigned)IH && (unsigned)ix<(unsigned)IW)
            v = X[pbase[j] + ic*(IH*IW) + iy*IW + ix];
          if(RELU_IN) v=fmaxf(v,0.f);
        }
        bN[j]=v;
      }
    }
#pragma unroll
    for(int k=0;k<BK;k++){
      float4 a0 = *(const float4*)&As[cur][k][ty4];
      float4 a1 = *(const float4*)&As[cur][k][ty4+64];
      ulonglong2 B0 = *(const ulonglong2*)&Bs[cur][k][tx4];
      ulonglong2 B1 = *(const ulonglong2*)&Bs[cur][k][tx4+64];
      float av[8] = {a0.x,a0.y,a0.z,a0.w,a1.x,a1.y,a1.z,a1.w};
#pragma unroll
      for(int i=0;i<8;i++){
        unsigned long long ad = fdup(av[i]);
        ffma2(acc[i][0],ad,B0.x);
        ffma2(acc[i][1],ad,B0.y);
        ffma2(acc[i][2],ad,B1.x);
        ffma2(acc[i][3],ad,B1.y);
      }
    }
    if(more){
      As[nxt][ak+0][am]=aN.x; As[nxt][ak+1][am]=aN.y;
      As[nxt][ak+2][am]=aN.z; As[nxt][ak+3][am]=aN.w;
      *(float4*)&Bs[nxt][gk][gn] = make_float4(bN[0],bN[1],bN[2],bN[3]);
    }
    __syncthreads();
  }

  if(MODE==0){
    const int b = n0 / OHW;
    const int pbq = n0 - b*OHW;
#pragma unroll
    for(int i=0;i<8;i++){
      int m = m0 + ty4 + ((i<4) ? i : (60 + i));
      float bv = bias[m];
      float* op = out + ((long)b*OC + m)*OHW + pbq;
      float2 v0 = funpack(acc[i][0]); float2 v1 = funpack(acc[i][1]);
      float2 v2 = funpack(acc[i][2]); float2 v3 = funpack(acc[i][3]);
      float4 lo = make_float4(fmaxf(v0.x+bv,0.f), fmaxf(v0.y+bv,0.f),
                              fmaxf(v1.x+bv,0.f), fmaxf(v1.y+bv,0.f));
      float4 hi = make_float4(fmaxf(v2.x+bv,0.f), fmaxf(v2.y+bv,0.f),
                              fmaxf(v3.x+bv,0.f), fmaxf(v3.y+bv,0.f));
      *(float4*)(op + tx4)      = lo;
      *(float4*)(op + tx4 + 64) = hi;
    }
  } else if(MODE==2){
    // padded direct write: tile is one (b, oy) row segment
    const int b = n0 / OHW;
    int p = n0 - b*OHW; int oy = p/OW; int ox0 = p - oy*OW;
#pragma unroll
    for(int i=0;i<8;i++){
      int m = m0 + ty4 + ((i<4) ? i : (60 + i));
      float bv = bias[m];
      float* op = out + (((long)b*OC + m)*(OH+4) + (oy+2))*(OW+4) + ox0 + 2;
      float2 v0 = funpack(acc[i][0]); float2 v1 = funpack(acc[i][1]);
      float2 v2 = funpack(acc[i][2]); float2 v3 = funpack(acc[i][3]);
      v0.x=fmaxf(v0.x+bv,0.f); v0.y=fmaxf(v0.y+bv,0.f);
      v1.x=fmaxf(v1.x+bv,0.f); v1.y=fmaxf(v1.y+bv,0.f);
      v2.x=fmaxf(v2.x+bv,0.f); v2.y=fmaxf(v2.y+bv,0.f);
      v3.x=fmaxf(v3.x+bv,0.f); v3.y=fmaxf(v3.y+bv,0.f);
      *(float2*)(op + tx4)      = v0;
      *(float2*)(op + tx4 + 2)  = v1;
      *(float2*)(op + tx4 + 64) = v2;
      *(float2*)(op + tx4 + 66) = v3;
    }
  } else {
#pragma unroll
    for(int i=0;i<8;i++){
      int m = m0 + ty4 + ((i<4) ? i : (60 + i));
      float* pp = out + ((long)blockIdx.z*OC + m)*Ntot + n0;
      float2 v0 = funpack(acc[i][0]); float2 v1 = funpack(acc[i][1]);
      float2 v2 = funpack(acc[i][2]); float2 v3 = funpack(acc[i][3]);
      *(float4*)(pp + tx4)      = make_float4(v0.x,v0.y,v1.x,v1.y);
      *(float4*)(pp + tx4 + 64) = make_float4(v2.x,v2.y,v3.x,v3.y);
    }
  }
}

// ---- split-K reduce + bias + residual-add + relu, NCHW write ----
__global__ void epilogue_k(const float* __restrict__ part, const float* __restrict__ bias,
                           const float* __restrict__ add, float* __restrict__ out,
                           int M, int N, int OHW, int nsplit, int relu)
{
  int gid = blockIdx.x*256 + threadIdx.x;
  if(gid >= M*N) return;
  int m = gid / N, n = gid - m*N;
  float s = 0.f;
  for(int sp=0; sp<nsplit; sp++) s += part[((long)sp*M + m)*N + n];
  if(bias) s += bias[m];
  int b = n / OHW, p = n - b*OHW;
  long oa = ((long)b*M + m)*OHW + p;
  if(add) s += add[oa];
  if(relu) s = fmaxf(s, 0.f);
  out[oa] = s;
}

// ---- VQ ----
__global__ void transpose_emb_k(const float* __restrict__ emb, float* __restrict__ embT){
  int gid = blockIdx.x*256 + threadIdx.x;   // 131072
  int d = gid >> 9, c = gid & 511;
  embT[gid] = emb[c*256 + d];
}

__global__ void emb_normsT_k(const float* __restrict__ embT, float* __restrict__ se){
  int c = blockIdx.x*256 + threadIdx.x;     // 512
  float s = 0.f;
  for(int d=0; d<256; d++){ float v = embT[d*512 + c]; s = fmaf(v,v,s); }
  se[c] = s;
}

__global__ void vq_rows_k(const float* __restrict__ lat, const float* __restrict__ embT,
                          const float* __restrict__ emb, const float* __restrict__ se,
                          int* __restrict__ idxo, float* __restrict__ sqo)
{
  __shared__ float sl[256];
  __shared__ float sval[256];
  __shared__ int   sidx[256];
  int r = blockIdx.x, t = threadIdx.x;
  int b = r >> 6, p = r & 63;
  sl[t] = lat[((b<<8) + t)*64 + p];
  __syncthreads();
  float fn = 0.f;
  for(int k=0;k<256;k++) fn = fmaf(sl[k], sl[k], fn);
  float d0 = 0.f, d1 = 0.f;
  for(int k=0;k<256;k++){
    float v = sl[k];
    d0 = fmaf(embT[k*512 + t],       v, d0);
    d1 = fmaf(embT[k*512 + t + 256], v, d1);
  }
  float dist0 = fn + se[t]     - 2.f*d0;
  float dist1 = fn + se[t+256] - 2.f*d1;
  float best; int bi;
  if(dist1 < dist0){ best = dist1; bi = t + 256; }
  else             { best = dist0; bi = t; }
  sval[t]=best; sidx[t]=bi;
  __syncthreads();
  for(int s=128;s>0;s>>=1){
    if(t<s){
      float v2=sval[t+s]; int i2=sidx[t+s];
      if(v2<sval[t] || (v2==sval[t] && i2<sidx[t])){ sval[t]=v2; sidx[t]=i2; }
    }
    __syncthreads();
  }
  int w = sidx[0];
  if(t==0) idxo[r]=w;
  __syncthreads();
  float diff = emb[w*256 + t] - sl[t];
  sval[t] = diff*diff;
  __syncthreads();
  for(int s=128;s>0;s>>=1){
    if(t<s) sval[t]+=sval[t+s];
    __syncthreads();
  }
  if(t==0) sqo[r]=sval[0];
}

__global__ void write_quant_k(const int* __restrict__ idx, const float* __restrict__ emb,
                              float* __restrict__ out){
  int gid = blockIdx.x*256 + threadIdx.x;   // 131072 total
  int p = gid & 63;
  int c = (gid >> 6) & 255;
  int b = gid >> 14;
  out[gid] = emb[idx[(b<<6)+p]*256 + c];
}

__global__ void finalize_k(const int* __restrict__ idx, const float* __restrict__ sq,
                           float* __restrict__ out2){
  __shared__ float sh[512];
  __shared__ float ss[512];
  int t = threadIdx.x;   // 512 threads
  int cnt = 0;
  for(int r=0;r<512;r++) cnt += (idx[r]==t) ? 1 : 0;
  float pr = (float)cnt * (1.f/512.f);
  sh[t] = -pr * logf(pr + 1e-10f);
  ss[t] = sq[t];
  __syncthreads();
  for(int s=256;s>0;s>>=1){
    if(t<s){ sh[t]+=sh[t+s]; ss[t]+=ss[t+s]; }
    __syncthreads();
  }
  if(t==0){
    out2[0] = 2.f * ss[0] * (1.f/131072.f);  // q_loss + BETA*e_loss
    out2[1] = expf(sh[0]);
  }
}

// ---------------- host ----------------
template<int IC,int IH,int IW,int OC,int OH,int OW,int KH,int KW,
         int SH,int SW,int PH,int PW,int NSPLIT,bool RIN,int MODE,bool PADIN>
static void launch_conv(const float* W, const float* X, const float* bias, float* out){
  dim3 g((8*OH*OW)/128, OC/128, NSPLIT);
  conv_gemm<IC,IH,IW,OC,OH,OW,KH,KW,SH,SW,PH,PW,NSPLIT,RIN,MODE,PADIN><<<g,256>>>(W,X,bias,out);
}

extern "C" void kernel_launch(void* const* d_in, const int* in_sizes, int n_in,
                              void* d_out, int out_size)
{
  const float* x     = (const float*)d_in[0];
  const float* w_in  = (const float*)d_in[1];
  const float* b_in  = (const float*)d_in[2];
  const float* w_h1  = (const float*)d_in[3];
  const float* b_h1  = (const float*)d_in[4];
  const float* w_h2  = (const float*)d_in[5];
  const float* b_h2  = (const float*)d_in[6];
  const float* w_h3  = (const float*)d_in[7];
  const float* b_h3  = (const float*)d_in[8];
  const float* r0_w1 = (const float*)d_in[9];
  const float* r0_w2 = (const float*)d_in[10];
  const float* r1_w1 = (const float*)d_in[11];
  const float* r1_w2 = (const float*)d_in[12];
  const float* emb   = (const float*)d_in[13];
  float* out = (float*)d_out;

  float *b1,*b2,*b3,*b4,*b5,*b6,*tr,*pp,*eT,*se,*sq; int* gi;
  cudaGetSymbolAddress((void**)&b1, g_buf1);
  cudaGetSymbolAddress((void**)&b2, g_buf2);
  cudaGetSymbolAddress((void**)&b3, g_buf3);
  cudaGetSymbolAddress((void**)&b4, g_buf4);
  cudaGetSymbolAddress((void**)&b5, g_buf5);
  cudaGetSymbolAddress((void**)&b6, g_buf6);
  cudaGetSymbolAddress((void**)&tr, g_tres);
  cudaGetSymbolAddress((void**)&pp, g_part);
  cudaGetSymbolAddress((void**)&eT, g_embT);
  cudaGetSymbolAddress((void**)&se, g_se);
  cudaGetSymbolAddress((void**)&sq, g_sqn);
  cudaGetSymbolAddress((void**)&gi, g_idx);

  // idx 0-2 padding; idx 3 = h1 is the ncu-profiled launch (-s 5 skips 2 harness + 3 here... 
  // empirically profiled slot = our 4th launch)
  transpose_emb_k<<<512,256>>>(emb, eT);                                        // 0
  emb_normsT_k<<<2,256>>>(eT, se);                                              // 1
  // conv_in: [8,3,512,512] -> PADDED [8,128,260,260], 4x4 s2 p1, bias+relu
  launch_conv<3,512,512, 128,256,256, 4,4, 2,2, 1,1, 1,false,2,false>(w_in, x, b_in, b1);  // 2
  // h1 (PROFILED): padded in -> [8,256,64,64], 7x7 s4 p2, bias+relu, direct
  launch_conv<128,256,256, 256,64,64, 7,7, 4,4, 2,2, 1,false,0,true>(w_h1, b1, b_h1, b2);  // 3
  // h2: -> [8,256,16,16], 7x7 s4 p2, split-K 8
  launch_conv<256,64,64, 256,16,16, 7,7, 4,4, 2,2, 8,false,1,false>(w_h2, b2, nullptr, pp);
  epilogue_k<<<(256*2048+255)/256,256>>>(pp, b_h2, nullptr, b3, 256, 2048, 256, 8, 1);
  // h3: -> [8,256,8,8], 3x3 s2 p1, split-K 16
  launch_conv<256,16,16, 256,8,8, 3,3, 2,2, 1,1, 16,false,1,false>(w_h3, b3, nullptr, pp);
  epilogue_k<<<(256*512+255)/256,256>>>(pp, b_h3, nullptr, b4, 256, 512, 64, 16, 1);

  // residual block 0 (input b4 >= 0, relu(h)==h)
  launch_conv<256,8,8, 1024,8,8, 1,3, 1,1, 0,1, 8,false,1,false>(r0_w1, b4, nullptr, pp);
  epilogue_k<<<(1024*512+255)/256,256>>>(pp, nullptr, nullptr, tr, 1024, 512, 64, 8, 1);
  launch_conv<1024,8,8, 256,8,8, 1,1, 1,1, 0,0, 8,false,1,false>(r0_w2, tr, nullptr, pp);
  epilogue_k<<<(256*512+255)/256,256>>>(pp, nullptr, b4, b5, 256, 512, 64, 8, 0);

  // residual block 1 (b5 may be negative -> relu on gather)
  launch_conv<256,8,8, 1024,8,8, 1,3, 1,1, 0,1, 8,true,1,false>(r1_w1, b5, nullptr, pp);
  epilogue_k<<<(1024*512+255)/256,256>>>(pp, nullptr, nullptr, tr, 1024, 512, 64, 8, 1);
  launch_conv<1024,8,8, 256,8,8, 1,1, 1,1, 0,0, 8,false,1,false>(r1_w2, tr, nullptr, pp);
  // h = relu(b5 + t)  (final relu before VQ folded here)
  epilogue_k<<<(256*512+255)/256,256>>>(pp, nullptr, b5, b6, 256, 512, 64, 8, 1);

  // VQ
  vq_rows_k<<<512,256>>>(b6, eT, emb, se, gi, sq);
  write_quant_k<<<512,256>>>(gi, emb, out);
  finalize_k<<<1,512>>>(gi, sq, out + 131072);
}